// round 3
// baseline (speedup 1.0000x reference)
#include <cuda_runtime.h>
#include <math.h>
#include <stdint.h>

#define N_NODES 4096
#define FIN 20
#define H 4
#define D 64
#define TILE_C 64
#define ROWS_PER_BLK 32

// per-buffer smem layout (floats): whs[H][64][64]=16384, adj[32][65]=2080, fd[H][64]=256
#define BUF_FLOATS (16384 + 2080 + 256)
#define SMEM_BYTES (2 * BUF_FLOATS * 4)

// ---------------- device scratch (no allocations allowed) ----------------
__device__ float g_Wh[H * N_NODES * D];     // 4 MB, reused for both layers
__device__ float g_fs[H * N_NODES];
__device__ float g_fd[H * N_NODES];
__device__ float g_maxfd[H];
__device__ float g_h1[N_NODES * H * D];     // layer-0 concat output, 4 MB

// ---------------- helpers ----------------
__device__ __forceinline__ float wsum(float v) {
#pragma unroll
    for (int s = 16; s > 0; s >>= 1) v += __shfl_xor_sync(0xffffffffu, v, s);
    return v;
}

__device__ __forceinline__ unsigned long long pack2(float x) {
    unsigned long long r;
    asm("mov.b64 %0, {%1, %1};" : "=l"(r) : "f"(x));
    return r;
}

__device__ __forceinline__ void fma2(unsigned long long& d, unsigned long long a,
                                     unsigned long long b) {
    // packed f32x2 FMA: d = a*b + d (two fp32 lanes per instruction; ptxas
    // never auto-fuses this from C++ — PTX-only, per SASS_QUICKREF)
    asm("fma.rn.f32x2 %0, %1, %2, %0;" : "+l"(d) : "l"(a), "l"(b));
}

__device__ __forceinline__ float elu_f(float x) {
    return x > 0.f ? x : expm1f(x);
}

__device__ __forceinline__ void cp16(uint32_t s, const void* g) {
    asm volatile("cp.async.cg.shared.global [%0], [%1], 16;" :: "r"(s), "l"(g));
}
__device__ __forceinline__ void cp4(uint32_t s, const void* g) {
    asm volatile("cp.async.ca.shared.global [%0], [%1], 4;" :: "r"(s), "l"(g));
}
__device__ __forceinline__ void cp_commit() {
    asm volatile("cp.async.commit_group;");
}
__device__ __forceinline__ void cp_wait0() {
    asm volatile("cp.async.wait_group 0;");
}

// ---------------- layer-0 projection: Wh0 = x @ W0, plus fs/fd ----------------
__global__ void k_wh0(const float* __restrict__ x, const float* __restrict__ W0,
                      const float* __restrict__ a0) {
    int n = blockIdx.x, h = blockIdx.y, o = threadIdx.x;  // 64 threads
    __shared__ float xs[FIN];
    if (o < FIN) xs[o] = __ldg(x + n * FIN + o);
    __syncthreads();
    float wh = 0.f;
#pragma unroll
    for (int f = 0; f < FIN; f++) wh += xs[f] * W0[(h * FIN + f) * D + o];
    g_Wh[(h * N_NODES + n) * D + o] = wh;

    float ps = wsum(wh * __ldg(a0 + h * 2 * D + o));
    float pd = wsum(wh * __ldg(a0 + h * 2 * D + D + o));
    __shared__ float rb[2][2];
    if ((o & 31) == 0) { rb[0][o >> 5] = ps; rb[1][o >> 5] = pd; }
    __syncthreads();
    if (o == 0) {
        g_fs[h * N_NODES + n] = rb[0][0] + rb[0][1];
        g_fd[h * N_NODES + n] = rb[1][0] + rb[1][1];
    }
}

// ---------------- layer-1 projection: Wh1 = h1 @ W1, plus fs/fd ----------------
__global__ void k_wh1(const float* __restrict__ W1, const float* __restrict__ a1) {
    int h = blockIdx.y;
    int n0 = blockIdx.x * 4;
    int o = threadIdx.x;  // 64 threads
    __shared__ float hs[4][H * D];
    for (int idx = o; idx < 4 * H * D; idx += 64) {
        int r = idx >> 8, f = idx & (H * D - 1);
        hs[r][f] = g_h1[(n0 + r) * (H * D) + f];
    }
    __syncthreads();
    float wh[4] = {0.f, 0.f, 0.f, 0.f};
    for (int f = 0; f < H * D; f++) {
        float w = W1[(h * H * D + f) * D + o];
#pragma unroll
        for (int r = 0; r < 4; r++) wh[r] += hs[r][f] * w;
    }
#pragma unroll
    for (int r = 0; r < 4; r++) g_Wh[(h * N_NODES + n0 + r) * D + o] = wh[r];

    float as = __ldg(a1 + h * 2 * D + o), ad = __ldg(a1 + h * 2 * D + D + o);
    __shared__ float rbuf[2][2][4];
    int w = o >> 5, lane = o & 31;
#pragma unroll
    for (int r = 0; r < 4; r++) {
        float ps = wsum(wh[r] * as);
        float pd = wsum(wh[r] * ad);
        if (lane == 0) { rbuf[0][w][r] = ps; rbuf[1][w][r] = pd; }
    }
    __syncthreads();
    if (o < 4) {
        g_fs[h * N_NODES + n0 + o] = rbuf[0][0][o] + rbuf[0][1][o];
        g_fd[h * N_NODES + n0 + o] = rbuf[1][0][o] + rbuf[1][1][o];
    }
}

// ---------------- per-head max of fd (fixed softmax shift) ----------------
__global__ void k_maxfd() {
    int h = blockIdx.x;
    float mx = -1e30f;
    for (int j = threadIdx.x; j < N_NODES; j += 256)
        mx = fmaxf(mx, g_fd[h * N_NODES + j]);
#pragma unroll
    for (int s = 16; s > 0; s >>= 1) mx = fmaxf(mx, __shfl_xor_sync(0xffffffffu, mx, s));
    __shared__ float sm[8];
    if ((threadIdx.x & 31) == 0) sm[threadIdx.x >> 5] = mx;
    __syncthreads();
    if (threadIdx.x == 0) {
        float r = sm[0];
#pragma unroll
        for (int i = 1; i < 8; i++) r = fmaxf(r, sm[i]);
        g_maxfd[h] = r;
    }
}

// ---------------- async tile stage: Wh tile (4 heads), adj tile, fd tile ----------------
__device__ __forceinline__ void stage_tile(float* buf, int rowbase, int jbase,
                                           const int* __restrict__ adj, int tid) {
    uint32_t sw = (uint32_t)__cvta_generic_to_shared(buf);
    uint32_t sa = sw + 16384u * 4u;
    uint32_t sf = sa + 2080u * 4u;
    const char* Wg = (const char*)g_Wh;
    // Wh tile: [H][64 j][64 c] -> 4096 x 16B
#pragma unroll
    for (int v = tid; v < 4096; v += 128) {
        int hh = v >> 10;
        int j = (v >> 4) & 63;
        int c = v & 15;
        cp16(sw + (uint32_t)v * 16u,
             Wg + ((size_t)((hh * N_NODES + jbase + j) * 16 + c)) * 16u);
    }
    // adj tile: [32 r][64 c] stored padded to 65 ints/row; lane r reads
    // adjs[r*65+j] -> bank (r+j) mod 32, all distinct -> conflict-free
#pragma unroll
    for (int idx = tid; idx < 2048; idx += 128) {
        int r = idx >> 6, c = idx & 63;
        cp4(sa + (uint32_t)(r * 65 + c) * 4u,
            adj + (size_t)(rowbase + r) * N_NODES + jbase + c);
    }
    // fd tile: [H][64]
#pragma unroll
    for (int idx = tid; idx < 256; idx += 128) {
        int hh = idx >> 6, j = idx & 63;
        cp4(sf + (uint32_t)idx * 4u, g_fd + hh * N_NODES + jbase + j);
    }
    cp_commit();
}

// ---------------- fused flash-style GAT attention ----------------
// block = 128 threads: warp = head, lane = row within 32-row block.
// Single-pass softmax: m = lrelu(fs_i + max_j fd_j) is a valid fixed shift
// (lrelu monotone + softmax shift-invariance) -> no rescaling needed.
template <bool AVG>
__global__ void __launch_bounds__(128)
k_attn(const int* __restrict__ adj, float* __restrict__ out) {
    extern __shared__ float smem[];

    int tid = threadIdx.x;
    int lane = tid & 31;
    int h = tid >> 5;
    int rowbase = blockIdx.x * ROWS_PER_BLK;
    int i = rowbase + lane;

    float my_fs = g_fs[h * N_NODES + i];
    float m = my_fs + g_maxfd[h];
    m = fmaxf(m, 0.2f * m);

    unsigned long long acc2[32];
#pragma unroll
    for (int c = 0; c < 32; c++) acc2[c] = 0ull;
    float l = 0.f;

    // preload tile 0
    stage_tile(smem, rowbase, 0, adj, tid);
    cp_wait0();
    __syncthreads();

    for (int jb = 0; jb < N_NODES / TILE_C; jb++) {
        float* cur = smem + (jb & 1) * BUF_FLOATS;
        float* nxt = smem + ((jb + 1) & 1) * BUF_FLOATS;
        if (jb + 1 < N_NODES / TILE_C)
            stage_tile(nxt, rowbase, (jb + 1) * TILE_C, adj, tid);

        const int* adjs = (const int*)(cur + 16384);
        const float* fds = cur + 16384 + 2080;
        const float* whs = cur;

#pragma unroll 4
        for (int j = 0; j < TILE_C; j++) {
            int a = adjs[lane * 65 + j];
            float e = my_fs + fds[h * 64 + j];
            e = fmaxf(e, 0.2f * e);                 // LeakyReLU(0.2)
            float ex = __expf(e - m);
            float p = a ? ex : 0.f;
            l += p;
            unsigned long long p2 = pack2(p);
            const ulonglong2* w2 =
                reinterpret_cast<const ulonglong2*>(whs + (h * 64 + j) * 64);
#pragma unroll
            for (int c = 0; c < 16; c++) {
                ulonglong2 v = w2[c];
                fma2(acc2[2 * c], v.x, p2);
                fma2(acc2[2 * c + 1], v.y, p2);
            }
        }
        cp_wait0();
        __syncthreads();
    }

    float inv = 1.0f / fmaxf(l, 1e-30f);

    if (!AVG) {
        // layer 0: write elu(out) concatenated: h1[i][h*64 + k]
        float4* dst = reinterpret_cast<float4*>(g_h1 + i * (H * D) + h * D);
#pragma unroll
        for (int c = 0; c < 16; c++) {
            float2 lo = *reinterpret_cast<float2*>(&acc2[2 * c]);
            float2 hi = *reinterpret_cast<float2*>(&acc2[2 * c + 1]);
            float4 v;
            v.x = elu_f(lo.x * inv);
            v.y = elu_f(lo.y * inv);
            v.z = elu_f(hi.x * inv);
            v.w = elu_f(hi.y * inv);
            dst[c] = v;
        }
    } else {
        // layer 1: elu then average over heads via smem (reuse buffer 0)
        float* red = smem;  // [H][32][64]
#pragma unroll
        for (int c = 0; c < 32; c++) {
            float2 t = *reinterpret_cast<float2*>(&acc2[c]);
            red[(h * 32 + lane) * 64 + 2 * c] = elu_f(t.x * inv);
            red[(h * 32 + lane) * 64 + 2 * c + 1] = elu_f(t.y * inv);
        }
        __syncthreads();
        for (int idx = tid; idx < ROWS_PER_BLK * D; idx += 128) {
            int r = idx >> 6, k = idx & 63;
            float s = 0.25f * (red[(0 * 32 + r) * 64 + k] + red[(1 * 32 + r) * 64 + k] +
                               red[(2 * 32 + r) * 64 + k] + red[(3 * 32 + r) * 64 + k]);
            out[(rowbase + r) * D + k] = s;
        }
    }
}

// ---------------- launch ----------------
extern "C" void kernel_launch(void* const* d_in, const int* in_sizes, int n_in,
                              void* d_out, int out_size) {
    const float* x = (const float*)d_in[0];
    const int* adj = (const int*)d_in[1];
    const float* W0 = (const float*)d_in[2];
    const float* a0 = (const float*)d_in[3];
    const float* W1 = (const float*)d_in[4];
    const float* a1 = (const float*)d_in[5];
    float* out = (float*)d_out;

    cudaFuncSetAttribute(k_attn<false>, cudaFuncAttributeMaxDynamicSharedMemorySize,
                         SMEM_BYTES);
    cudaFuncSetAttribute(k_attn<true>, cudaFuncAttributeMaxDynamicSharedMemorySize,
                         SMEM_BYTES);

    // layer 0
    k_wh0<<<dim3(N_NODES, H), 64>>>(x, W0, a0);
    k_maxfd<<<H, 256>>>();
    k_attn<false><<<N_NODES / ROWS_PER_BLK, 128, SMEM_BYTES>>>(adj, nullptr);

    // layer 1
    k_wh1<<<dim3(N_NODES / 4, H), 64>>>(W1, a1);
    k_maxfd<<<H, 256>>>();
    k_attn<true><<<N_NODES / ROWS_PER_BLK, 128, SMEM_BYTES>>>(adj, out);
}

// round 4
// speedup vs baseline: 1.0568x; 1.0568x over previous
#include <cuda_runtime.h>
#include <math.h>
#include <stdint.h>

#define N_NODES 4096
#define FIN 20
#define H 4
#define D 64
#define TILE_C 64
#define ROWS_PER_BLK 32

// per-buffer smem layout (floats): whs[H][64][64]=16384, adj[32][65]=2080, fd[H][64]=256
#define BUF_FLOATS (16384 + 2080 + 256)
#define SMEM_BYTES (2 * BUF_FLOATS * 4)
#define WH1_SMEM (128 * 256 * 4)

// ---------------- device scratch (no allocations allowed) ----------------
__device__ float g_Wh[H * N_NODES * D];     // 4 MB, reused for both layers
__device__ float g_fs[H * N_NODES];
__device__ float g_fd[H * N_NODES];
__device__ float g_maxfd[H];
__device__ float g_h1[N_NODES * H * D];     // layer-0 concat output, 4 MB

// ---------------- helpers ----------------
__device__ __forceinline__ float wsum(float v) {
#pragma unroll
    for (int s = 16; s > 0; s >>= 1) v += __shfl_xor_sync(0xffffffffu, v, s);
    return v;
}

__device__ __forceinline__ unsigned long long pack2(float x) {
    unsigned long long r;
    asm("mov.b64 %0, {%1, %1};" : "=l"(r) : "f"(x));
    return r;
}

__device__ __forceinline__ void fma2(unsigned long long& d, unsigned long long a,
                                     unsigned long long b) {
    // packed f32x2 FMA (PTX-only; ptxas never auto-fuses from C++)
    asm("fma.rn.f32x2 %0, %1, %2, %0;" : "+l"(d) : "l"(a), "l"(b));
}

__device__ __forceinline__ float elu_f(float x) {
    return x > 0.f ? x : expm1f(x);
}

__device__ __forceinline__ void cp16(uint32_t s, const void* g) {
    asm volatile("cp.async.cg.shared.global [%0], [%1], 16;" :: "r"(s), "l"(g));
}
__device__ __forceinline__ void cp4(uint32_t s, const void* g) {
    asm volatile("cp.async.ca.shared.global [%0], [%1], 4;" :: "r"(s), "l"(g));
}
__device__ __forceinline__ void cp_commit() {
    asm volatile("cp.async.commit_group;");
}
__device__ __forceinline__ void cp_wait0() {
    asm volatile("cp.async.wait_group 0;");
}

// ---------------- layer-0 projection: Wh0 = x @ W0, plus fs/fd ----------------
// grid (N/8, H), block 64. 8 nodes per block.
__global__ void k_wh0(const float* __restrict__ x, const float* __restrict__ W0,
                      const float* __restrict__ a0) {
    int h = blockIdx.y, o = threadIdx.x;
    int n0 = blockIdx.x * 8;
    __shared__ float xs[8][FIN];
    for (int idx = o; idx < 8 * FIN; idx += 64)
        xs[idx / FIN][idx % FIN] = x[n0 * FIN + idx];
    __syncthreads();
    float wh[8] = {0.f, 0.f, 0.f, 0.f, 0.f, 0.f, 0.f, 0.f};
#pragma unroll
    for (int f = 0; f < FIN; f++) {
        float w = W0[(h * FIN + f) * D + o];
#pragma unroll
        for (int r = 0; r < 8; r++) wh[r] += xs[r][f] * w;
    }
#pragma unroll
    for (int r = 0; r < 8; r++) g_Wh[(h * N_NODES + n0 + r) * D + o] = wh[r];

    float as = __ldg(a0 + h * 2 * D + o), ad = __ldg(a0 + h * 2 * D + D + o);
    __shared__ float rb[2][2][8];
    int w = o >> 5, lane = o & 31;
#pragma unroll
    for (int r = 0; r < 8; r++) {
        float ps = wsum(wh[r] * as);
        float pd = wsum(wh[r] * ad);
        if (lane == 0) { rb[0][w][r] = ps; rb[1][w][r] = pd; }
    }
    __syncthreads();
    if (o < 8) {
        g_fs[h * N_NODES + n0 + o] = rb[0][0][o] + rb[0][1][o];
        g_fd[h * N_NODES + n0 + o] = rb[1][0][o] + rb[1][1][o];
    }
}

// ---------------- layer-1 projection: Wh1 = h1 @ W1, plus fs/fd ----------------
// grid (32, H), block 256, dyn smem 128KB. CTA = 128 rows x 64 cols.
// thread (o2 = tid&31, rq = tid>>5): cols {2*o2, 2*o2+1}, rows rq*16..rq*16+15.
__global__ void __launch_bounds__(256)
k_wh1(const float* __restrict__ W1, const float* __restrict__ a1) {
    extern __shared__ float hs[];  // [128 rows][256 f]
    int h = blockIdx.y;
    int n0 = blockIdx.x * 128;
    int tid = threadIdx.x;
    int o2 = tid & 31;
    int rq = tid >> 5;

    // stage 128 rows of h1 (32768 floats = 8192 float4)
    const float4* src = reinterpret_cast<const float4*>(g_h1 + (size_t)n0 * (H * D));
    float4* dstv = reinterpret_cast<float4*>(hs);
#pragma unroll
    for (int v = tid; v < 8192; v += 256) dstv[v] = src[v];
    __syncthreads();

    unsigned long long acc[16];
#pragma unroll
    for (int r = 0; r < 16; r++) acc[r] = 0ull;

    const float* Wp = W1 + (size_t)h * (H * D) * D + 2 * o2;
    const float* hbase = hs + (rq * 16) * (H * D);
    for (int f = 0; f < H * D; f++) {
        unsigned long long w2 =
            *reinterpret_cast<const unsigned long long*>(Wp + (size_t)f * D);
#pragma unroll
        for (int r = 0; r < 16; r++)
            fma2(acc[r], pack2(hbase[r * (H * D) + f]), w2);
    }

    // write Wh (16 rows x 2 cols, STG.64, coalesced across lanes)
#pragma unroll
    for (int r = 0; r < 16; r++) {
        float2 t = *reinterpret_cast<float2*>(&acc[r]);
        *reinterpret_cast<float2*>(g_Wh + ((size_t)(h * N_NODES + n0 + rq * 16 + r)) * D +
                                   2 * o2) = t;
    }

    // fs/fd: dot over cols (lane o2 holds cols 2o2,2o2+1), warp-reduce over lanes
    float2 as2 = *reinterpret_cast<const float2*>(a1 + h * 2 * D + 2 * o2);
    float2 ad2 = *reinterpret_cast<const float2*>(a1 + h * 2 * D + D + 2 * o2);
    __shared__ float rb[2][8][16];
#pragma unroll
    for (int r = 0; r < 16; r++) {
        float2 t = *reinterpret_cast<float2*>(&acc[r]);
        float ps = wsum(t.x * as2.x + t.y * as2.y);
        float pd = wsum(t.x * ad2.x + t.y * ad2.y);
        if (o2 == 0) { rb[0][rq][r] = ps; rb[1][rq][r] = pd; }
    }
    __syncthreads();
    if (tid < 128) {
        g_fs[h * N_NODES + n0 + tid] = rb[0][tid >> 4][tid & 15];
    } else {
        int r = tid - 128;
        g_fd[h * N_NODES + n0 + r] = rb[1][r >> 4][r & 15];
    }
}

// ---------------- per-head max of fd (fixed softmax shift) ----------------
__global__ void k_maxfd() {
    int h = blockIdx.x;
    float mx = -1e30f;
    for (int j = threadIdx.x; j < N_NODES; j += 256)
        mx = fmaxf(mx, g_fd[h * N_NODES + j]);
#pragma unroll
    for (int s = 16; s > 0; s >>= 1) mx = fmaxf(mx, __shfl_xor_sync(0xffffffffu, mx, s));
    __shared__ float sm[8];
    if ((threadIdx.x & 31) == 0) sm[threadIdx.x >> 5] = mx;
    __syncthreads();
    if (threadIdx.x == 0) {
        float r = sm[0];
#pragma unroll
        for (int i = 1; i < 8; i++) r = fmaxf(r, sm[i]);
        g_maxfd[h] = r;
    }
}

// ---------------- async tile stage (256-thread version) ----------------
__device__ __forceinline__ void stage_tile(float* buf, int rowbase, int jbase,
                                           const int* __restrict__ adj, int tid) {
    uint32_t sw = (uint32_t)__cvta_generic_to_shared(buf);
    uint32_t sa = sw + 16384u * 4u;
    uint32_t sf = sa + 2080u * 4u;
    const char* Wg = (const char*)g_Wh;
    // Wh tile: [H][64 j][64 c] -> 4096 x 16B
#pragma unroll
    for (int v = tid; v < 4096; v += 256) {
        int hh = v >> 10;
        int j = (v >> 4) & 63;
        int c = v & 15;
        cp16(sw + (uint32_t)v * 16u,
             Wg + ((size_t)((hh * N_NODES + jbase + j) * 16 + c)) * 16u);
    }
    // adj tile: [32 r][64 c] padded to 65 ints/row (conflict-free column reads)
#pragma unroll
    for (int idx = tid; idx < 2048; idx += 256) {
        int r = idx >> 6, c = idx & 63;
        cp4(sa + (uint32_t)(r * 65 + c) * 4u,
            adj + (size_t)(rowbase + r) * N_NODES + jbase + c);
    }
    // fd tile: [H][64]
    if (tid < 256) {
        int hh = tid >> 6, j = tid & 63;
        cp4(sf + (uint32_t)tid * 4u, g_fd + hh * N_NODES + jbase + j);
    }
    cp_commit();
}

// ---------------- fused flash-style GAT attention ----------------
// block = 256 threads = 8 warps: warp w -> head (w&3), j-half (w>>2).
// Both halves share tiles; exp partial sums combine exactly (fixed shift m).
template <bool AVG>
__global__ void __launch_bounds__(256)
k_attn(const int* __restrict__ adj, float* __restrict__ out) {
    extern __shared__ float smem[];

    int tid = threadIdx.x;
    int lane = tid & 31;
    int w = tid >> 5;
    int h = w & 3;
    int jgroup = w >> 2;               // 0: j in [0,32), 1: j in [32,64) per tile
    int rowbase = blockIdx.x * ROWS_PER_BLK;
    int i = rowbase + lane;

    float my_fs = g_fs[h * N_NODES + i];
    float m = my_fs + g_maxfd[h];
    m = fmaxf(m, 0.2f * m);

    unsigned long long acc2[32];
#pragma unroll
    for (int c = 0; c < 32; c++) acc2[c] = 0ull;
    float l = 0.f;

    // preload tile 0
    stage_tile(smem, rowbase, 0, adj, tid);
    cp_wait0();
    __syncthreads();

    int j0 = jgroup * 32;
    for (int jb = 0; jb < N_NODES / TILE_C; jb++) {
        float* cur = smem + (jb & 1) * BUF_FLOATS;
        float* nxt = smem + ((jb + 1) & 1) * BUF_FLOATS;
        if (jb + 1 < N_NODES / TILE_C)
            stage_tile(nxt, rowbase, (jb + 1) * TILE_C, adj, tid);

        const int* adjs = (const int*)(cur + 16384);
        const float* fds = cur + 16384 + 2080;
        const float* whs = cur;

#pragma unroll 4
        for (int jj = 0; jj < 32; jj++) {
            int j = j0 + jj;
            int a = adjs[lane * 65 + j];
            float e = my_fs + fds[h * 64 + j];
            e = fmaxf(e, 0.2f * e);                 // LeakyReLU(0.2)
            float ex = __expf(e - m);
            float p = a ? ex : 0.f;
            l += p;
            unsigned long long p2 = pack2(p);
            const ulonglong2* w2 =
                reinterpret_cast<const ulonglong2*>(whs + (h * 64 + j) * 64);
#pragma unroll
            for (int c = 0; c < 16; c++) {
                ulonglong2 v = w2[c];
                fma2(acc2[2 * c], v.x, p2);
                fma2(acc2[2 * c + 1], v.y, p2);
            }
        }
        cp_wait0();
        __syncthreads();
    }

    // ---- combine the two j-halves (buffers no longer needed) ----
    float* redA = smem;                 // [128][66] floats
    float* l_red = smem + 8448;         // [128]
    float* redB = smem + 8704;          // [H][32][64] for AVG path

    if (jgroup == 1) {
        float* row = redA + (h * 32 + lane) * 66;
#pragma unroll
        for (int c = 0; c < 32; c++)
            reinterpret_cast<float2*>(row)[c] = *reinterpret_cast<float2*>(&acc2[c]);
        l_red[h * 32 + lane] = l;
    }
    __syncthreads();

    if (jgroup == 0) {
        const float* row = redA + (h * 32 + lane) * 66;
        l += l_red[h * 32 + lane];
        float inv = 1.0f / fmaxf(l, 1e-30f);
        if (!AVG) {
            float4* dst = reinterpret_cast<float4*>(g_h1 + i * (H * D) + h * D);
#pragma unroll
            for (int c = 0; c < 16; c++) {
                float2 a0v = *reinterpret_cast<float2*>(&acc2[2 * c]);
                float2 a1v = *reinterpret_cast<float2*>(&acc2[2 * c + 1]);
                float2 b0v = reinterpret_cast<const float2*>(row)[2 * c];
                float2 b1v = reinterpret_cast<const float2*>(row)[2 * c + 1];
                float4 v;
                v.x = elu_f((a0v.x + b0v.x) * inv);
                v.y = elu_f((a0v.y + b0v.y) * inv);
                v.z = elu_f((a1v.x + b1v.x) * inv);
                v.w = elu_f((a1v.y + b1v.y) * inv);
                dst[c] = v;
            }
        } else {
#pragma unroll
            for (int c = 0; c < 32; c++) {
                float2 av = *reinterpret_cast<float2*>(&acc2[c]);
                float2 bv = reinterpret_cast<const float2*>(row)[c];
                redB[(h * 32 + lane) * 64 + 2 * c] = elu_f((av.x + bv.x) * inv);
                redB[(h * 32 + lane) * 64 + 2 * c + 1] = elu_f((av.y + bv.y) * inv);
            }
        }
    }

    if (AVG) {
        __syncthreads();
        for (int idx = tid; idx < ROWS_PER_BLK * D; idx += 256) {
            int r = idx >> 6, k = idx & 63;
            float s = 0.25f * (redB[(0 * 32 + r) * 64 + k] + redB[(1 * 32 + r) * 64 + k] +
                               redB[(2 * 32 + r) * 64 + k] + redB[(3 * 32 + r) * 64 + k]);
            out[(rowbase + r) * D + k] = s;
        }
    }
}

// ---------------- launch ----------------
extern "C" void kernel_launch(void* const* d_in, const int* in_sizes, int n_in,
                              void* d_out, int out_size) {
    const float* x = (const float*)d_in[0];
    const int* adj = (const int*)d_in[1];
    const float* W0 = (const float*)d_in[2];
    const float* a0 = (const float*)d_in[3];
    const float* W1 = (const float*)d_in[4];
    const float* a1 = (const float*)d_in[5];
    float* out = (float*)d_out;

    cudaFuncSetAttribute(k_attn<false>, cudaFuncAttributeMaxDynamicSharedMemorySize,
                         SMEM_BYTES);
    cudaFuncSetAttribute(k_attn<true>, cudaFuncAttributeMaxDynamicSharedMemorySize,
                         SMEM_BYTES);
    cudaFuncSetAttribute(k_wh1, cudaFuncAttributeMaxDynamicSharedMemorySize, WH1_SMEM);

    // layer 0
    k_wh0<<<dim3(N_NODES / 8, H), 64>>>(x, W0, a0);
    k_maxfd<<<H, 256>>>();
    k_attn<false><<<N_NODES / ROWS_PER_BLK, 256, SMEM_BYTES>>>(adj, nullptr);

    // layer 1
    k_wh1<<<dim3(N_NODES / 128, H), 256, WH1_SMEM>>>(W1, a1);
    k_maxfd<<<H, 256>>>();
    k_attn<true><<<N_NODES / ROWS_PER_BLK, 256, SMEM_BYTES>>>(adj, out);
}